// round 2
// baseline (speedup 1.0000x reference)
#include <cuda_runtime.h>
#include <cuda_bf16.h>
#include <math.h>
#include <stdint.h>

// Problem shapes (fixed): B=4, S=2048, D=1024, H=1024
#define PB 4
#define PS 2048
#define PD 1024
#define PH 1024
#define PM (PB * PS)          // 8192 rows
#define EPSQ 1e-8f

// Scratch (static device arrays; allocation is forbidden)
__device__ float g_v[(size_t)PM * (3 * PH)];   // 8192 x 3072 (v = x W_in^T + b_in)
__device__ float g_q[(size_t)PM * (4 * PH)];   // 8192 x 4096 (quaternions, then states in-place)

// Packed dual-fp32 FMA (Blackwell f32x2 pipe; ptxas never auto-emits this)
#define FFMA_F32X2(d, a, b) \
    asm("fma.rn.f32x2 %0, %1, %2, %0;" : "+l"(d) : "l"(a), "l"(b))
#define PACK_DUP_F32X2(out, v) \
    asm("mov.b64 %0, {%1, %1};" : "=l"(out) : "r"(v))

// ---------------------------------------------------------------------------
// Quaternion helpers. float4 = (w, x, y, z)
// ---------------------------------------------------------------------------
__device__ __forceinline__ float4 qmul(float4 a, float4 b) {
    return make_float4(
        a.x * b.x - a.y * b.y - a.z * b.z - a.w * b.w,
        a.x * b.y + a.y * b.x + a.z * b.w - a.w * b.z,
        a.x * b.z - a.y * b.w + a.z * b.x + a.w * b.y,
        a.x * b.w + a.y * b.z - a.z * b.y + a.w * b.x);
}

__device__ __forceinline__ float4 qnorm(float4 a) {
    float n = sqrtf(a.x * a.x + a.y * a.y + a.z * a.z + a.w * a.w);
    float s = 1.0f / (n + EPSQ);
    return make_float4(a.x * s, a.y * s, a.z * s, a.w * s);
}

// ---------------------------------------------------------------------------
// SGEMM: C[M,N] = A[M,K] * B[N,K]^T + bias[N]
// 128x128 block tile, 8x8 per thread, BK=8, double-buffered smem.
// Inner product uses packed fma.rn.f32x2 (2 FMAs per instruction).
// ---------------------------------------------------------------------------
__global__ __launch_bounds__(256, 2)
void sgemm_nt_bias(const float* __restrict__ A, const float* __restrict__ B,
                   const float* __restrict__ bias, float* __restrict__ C,
                   int M, int N, int K) {
    __shared__ float As[2][8][128 + 4];
    __shared__ float Bs[2][8][128 + 4];

    const int tid = threadIdx.x;
    const int tx = tid & 15;        // 0..15  (N direction)
    const int ty = tid >> 4;        // 0..15  (M direction)
    const int crow = blockIdx.y * 128;
    const int ccol = blockIdx.x * 128;

    const int lrow = tid >> 1;           // 0..127
    const int lcol = (tid & 1) << 2;     // 0 or 4

    const float* Ag = A + (size_t)(crow + lrow) * K + lcol;
    const float* Bg = B + (size_t)(ccol + lrow) * K + lcol;

    // accumulators: 8 rows x 4 packed f32x2 (covering 8 N-columns)
    unsigned long long acc[8][4];
#pragma unroll
    for (int i = 0; i < 8; i++)
#pragma unroll
        for (int j = 0; j < 4; j++) acc[i][j] = 0ULL;

    // prologue: stage tile 0
    {
        float4 a4 = *(const float4*)Ag;
        float4 b4 = *(const float4*)Bg;
        As[0][lcol + 0][lrow] = a4.x; As[0][lcol + 1][lrow] = a4.y;
        As[0][lcol + 2][lrow] = a4.z; As[0][lcol + 3][lrow] = a4.w;
        Bs[0][lcol + 0][lrow] = b4.x; Bs[0][lcol + 1][lrow] = b4.y;
        Bs[0][lcol + 2][lrow] = b4.z; Bs[0][lcol + 3][lrow] = b4.w;
    }
    __syncthreads();

    int buf = 0;
    for (int kt = 8; kt <= K; kt += 8) {
        const bool more = (kt < K);
        float4 a4n, b4n;
        if (more) {
            a4n = *(const float4*)(Ag + kt);
            b4n = *(const float4*)(Bg + kt);
        }
#pragma unroll
        for (int k = 0; k < 8; k++) {
            float af[8];
            *(float4*)&af[0] = *(const float4*)&As[buf][k][ty * 8];
            *(float4*)&af[4] = *(const float4*)&As[buf][k][ty * 8 + 4];
            // B fragment as 4 packed f32x2 (64-bit aligned: tx*8 is even)
            union { float4 f[2]; unsigned long long u[4]; } bu;
            bu.f[0] = *(const float4*)&Bs[buf][k][tx * 8];
            bu.f[1] = *(const float4*)&Bs[buf][k][tx * 8 + 4];

            unsigned long long a2[8];
#pragma unroll
            for (int i = 0; i < 8; i++)
                PACK_DUP_F32X2(a2[i], __float_as_uint(af[i]));

#pragma unroll
            for (int i = 0; i < 8; i++) {
                FFMA_F32X2(acc[i][0], a2[i], bu.u[0]);
                FFMA_F32X2(acc[i][1], a2[i], bu.u[1]);
                FFMA_F32X2(acc[i][2], a2[i], bu.u[2]);
                FFMA_F32X2(acc[i][3], a2[i], bu.u[3]);
            }
        }
        if (more) {
            buf ^= 1;
            As[buf][lcol + 0][lrow] = a4n.x; As[buf][lcol + 1][lrow] = a4n.y;
            As[buf][lcol + 2][lrow] = a4n.z; As[buf][lcol + 3][lrow] = a4n.w;
            Bs[buf][lcol + 0][lrow] = b4n.x; Bs[buf][lcol + 1][lrow] = b4n.y;
            Bs[buf][lcol + 2][lrow] = b4n.z; Bs[buf][lcol + 3][lrow] = b4n.w;
            __syncthreads();
        }
    }

    // epilogue: add bias, write out
    float bv[8];
#pragma unroll
    for (int j = 0; j < 8; j++) bv[j] = bias[ccol + tx * 8 + j];
#pragma unroll
    for (int i = 0; i < 8; i++) {
        union { unsigned long long u[4]; float f[8]; } au;
#pragma unroll
        for (int j = 0; j < 4; j++) au.u[j] = acc[i][j];
        float* Crow = C + (size_t)(crow + ty * 8 + i) * N + ccol + tx * 8;
        float4 o0, o1;
        o0.x = au.f[0] + bv[0]; o0.y = au.f[1] + bv[1];
        o0.z = au.f[2] + bv[2]; o0.w = au.f[3] + bv[3];
        o1.x = au.f[4] + bv[4]; o1.y = au.f[5] + bv[5];
        o1.z = au.f[6] + bv[6]; o1.w = au.f[7] + bv[7];
        *(float4*)(Crow + 0) = o0;
        *(float4*)(Crow + 4) = o1;
    }
}

// ---------------------------------------------------------------------------
// SU(2) exp map: v (M x 3H) -> q (M x H x 4)
// ---------------------------------------------------------------------------
__global__ void qmap_kernel(const float* __restrict__ v, float* __restrict__ q) {
    int idx = blockIdx.x * blockDim.x + threadIdx.x;   // over M*H
    if (idx >= PM * PH) return;
    int m = idx >> 10;            // H = 1024
    int h = idx & 1023;
    const float* vp = v + (size_t)m * (3 * PH) + h * 3;
    float vx = vp[0], vy = vp[1], vz = vp[2];
    float th = sqrtf(vx * vx + vy * vy + vz * vz);
    float s, c;
    sincosf(th, &s, &c);
    float inv = s / (th + EPSQ);
    *(float4*)(q + (size_t)idx * 4) = make_float4(c, vx * inv, vy * inv, vz * inv);
}

// ---------------------------------------------------------------------------
// Parallel prefix product of quaternions along S, per (b, h) chain.
// ---------------------------------------------------------------------------
__global__ __launch_bounds__(256)
void quat_scan_kernel(float* __restrict__ q, float* __restrict__ mfinal) {
    const int b = blockIdx.x >> 10;        // H = 1024
    const int h = blockIdx.x & 1023;
    const int t = threadIdx.x;

    const size_t base = ((size_t)b * PS * PH + h) * 4;

    float4 loc[8];
#pragma unroll
    for (int j = 0; j < 8; j++)
        loc[j] = *(const float4*)(q + base + (size_t)(t * 8 + j) * (PH * 4));

    float4 agg = loc[0];
#pragma unroll
    for (int j = 1; j < 8; j++) agg = qmul(loc[j], agg);

    __shared__ float4 sbuf[256];
    sbuf[t] = agg;
    __syncthreads();

#pragma unroll
    for (int d = 1; d < 256; d <<= 1) {
        float4 other;
        const bool has = (t >= d);
        if (has) other = sbuf[t - d];
        __syncthreads();
        if (has) sbuf[t] = qmul(sbuf[t], other);
        __syncthreads();
    }

    float4 p = make_float4(1.0f, 0.0f, 0.0f, 0.0f);
    if (t > 0) p = sbuf[t - 1];

#pragma unroll
    for (int j = 0; j < 8; j++) {
        p = qmul(loc[j], p);
        float4 outq = qnorm(p);
        *(float4*)(q + base + (size_t)(t * 8 + j) * (PH * 4)) = outq;
        if (t == 255 && j == 7)
            *(float4*)(mfinal + (size_t)blockIdx.x * 4) = outq;
    }
}

// ---------------------------------------------------------------------------
extern "C" void kernel_launch(void* const* d_in, const int* in_sizes, int n_in,
                              void* d_out, int out_size) {
    const float* x     = (const float*)d_in[0];   // (B,S,D)
    const float* W_in  = (const float*)d_in[1];   // (3H, D)
    const float* b_in  = (const float*)d_in[2];   // (3H)
    const float* W_out = (const float*)d_in[3];   // (D, 4H)
    const float* b_out = (const float*)d_in[4];   // (D)
    float* out = (float*)d_out;
    float* full_output = out;                              // (B,S,D)
    float* m_final     = out + (size_t)PM * PD;            // (B,H,4)

    float* v_ptr = nullptr;
    float* q_ptr = nullptr;
    cudaGetSymbolAddress((void**)&v_ptr, g_v);
    cudaGetSymbolAddress((void**)&q_ptr, g_q);

    // 1) v = x W_in^T + b_in   (M=8192, N=3072, K=1024)
    {
        dim3 grid(3 * PH / 128, PM / 128);
        sgemm_nt_bias<<<grid, 256>>>(x, W_in, b_in, v_ptr, PM, 3 * PH, PD);
    }
    // 2) exp map -> quaternions
    {
        int total = PM * PH;
        qmap_kernel<<<(total + 255) / 256, 256>>>(v_ptr, q_ptr);
    }
    // 3) prefix quaternion product (replaces the sequential scan) + m_final
    {
        quat_scan_kernel<<<PB * PH, 256>>>(q_ptr, m_final);
    }
    // 4) out = states W_out^T + b_out   (M=8192, N=1024, K=4096)
    {
        dim3 grid(PD / 128, PM / 128);
        sgemm_nt_bias<<<grid, 256>>>(q_ptr, W_out, b_out, full_output, PM, PD, 4 * PH);
    }
}

// round 4
// speedup vs baseline: 2.4091x; 2.4091x over previous
#include <cuda_runtime.h>
#include <cuda_bf16.h>
#include <math.h>
#include <stdint.h>

// Problem shapes (fixed): B=4, S=2048, D=1024, H=1024
#define PB 4
#define PS 2048
#define PD 1024
#define PH 1024
#define PM (PB * PS)          // 8192 rows
#define EPSQ 1e-8f

// ---------------------------------------------------------------------------
// Static device scratch (allocation forbidden)
// ---------------------------------------------------------------------------
__device__ float g_v[(size_t)PM * (3 * PH)];            // 8192 x 3072
__device__ float g_q[(size_t)PM * (4 * PH)];            // 8192 x 4096 (quats -> states)
__device__ float g_a1[(size_t)PM * (3 * PD)];           // x 3xTF32:   8192 x 3072
__device__ float g_b1[(size_t)(3 * PH) * (3 * PD)];     // W_in 3xTF32: 3072 x 3072

// ---------------------------------------------------------------------------
// Helpers
// ---------------------------------------------------------------------------
__device__ __forceinline__ uint32_t smem_u32(const void* p) {
    uint32_t a;
    asm("{ .reg .u64 t; cvta.to.shared.u64 t, %1; cvt.u32.u64 %0, t; }" : "=r"(a) : "l"(p));
    return a;
}
__device__ __forceinline__ float tf32r(float a) {
    float r;
    asm("cvt.rna.tf32.f32 %0, %1;" : "=f"(r) : "f"(a));
    return r;
}
__device__ __forceinline__ void cp_async16(uint32_t dst, const void* src) {
    asm volatile("cp.async.cg.shared.global [%0], [%1], 16;" :: "r"(dst), "l"(src));
}

// ---------------------------------------------------------------------------
// 3xTF32 split: in (R x K) -> out (R x 3K)
//   modeB=0 (A operand): [hi | lo | hi]
//   modeB=1 (B operand): [hi | hi | lo]
// Product over K'=3K yields hi*hi + lo*hi + hi*lo  (error ~ eps^2)
// ---------------------------------------------------------------------------
__global__ void split3_kernel(const float* __restrict__ in, float* __restrict__ out,
                              int K, int modeB, size_t total4) {
    size_t s = (size_t)blockIdx.x * blockDim.x + threadIdx.x;
    if (s >= total4) return;
    int K4 = K >> 2;
    size_t row = s / K4;
    int c4 = (int)(s - row * K4);
    float4 a = ((const float4*)in)[s];
    float4 hi, lo;
    hi.x = tf32r(a.x); hi.y = tf32r(a.y); hi.z = tf32r(a.z); hi.w = tf32r(a.w);
    lo.x = tf32r(a.x - hi.x); lo.y = tf32r(a.y - hi.y);
    lo.z = tf32r(a.z - hi.z); lo.w = tf32r(a.w - hi.w);
    float4* orow = (float4*)(out + row * (size_t)(3 * K));
    orow[c4] = hi;
    if (modeB) { orow[c4 + K4] = hi; orow[c4 + 2 * K4] = lo; }
    else       { orow[c4 + K4] = lo; orow[c4 + 2 * K4] = hi; }
}

// ---------------------------------------------------------------------------
// mma.sync tf32 GEMM: C[M,N] = A[M,K] * B[N,K]^T + bias[N]
// CTA 128x128, 8 warps (2M x 4N) of 64x32, BK=32 floats, 3-stage cp.async.
// Operands are raw fp32 bits (HW truncates to tf32); pre-split data is exact.
// ---------------------------------------------------------------------------
#define BM 128
#define BN 128
#define BKF 32
#define GSTAGES 3
#define STAGE_BYTES 32768          // A 16KB + B 16KB
#define GSMEM (GSTAGES * STAGE_BYTES)

__global__ __launch_bounds__(256)
void gemm_tf32(const float* __restrict__ A, const float* __restrict__ B,
               const float* __restrict__ bias, float* __restrict__ C,
               int N, int K) {
    extern __shared__ char smem[];
    const uint32_t sbase = smem_u32(smem);

    const int tid = threadIdx.x;
    const int lane = tid & 31;
    const int wid = tid >> 5;
    const int wm = wid & 1;        // M warp (2)
    const int wn = wid >> 1;       // N warp (4)
    const int crow = blockIdx.y * BM;
    const int ccol = blockIdx.x * BN;
    const int T = K / BKF;

    const float* Abase = A + (size_t)crow * K;
    const float* Bbase = B + (size_t)ccol * K;

    // per-thread ldmatrix address components
    // A: lane groups -> (a0: rows 0-7,k0-3)(a1: rows 8-15,k0-3)(a2: 0-7,k4-7)(a3: 8-15,k4-7)
    const int aHalf = lane >> 4;               // c16 offset
    uint32_t aOff[4], aSwz[4];
#pragma unroll
    for (int mt = 0; mt < 4; mt++) {
        int r = wm * 64 + mt * 16 + (lane & 15);
        aOff[mt] = r * 128;
        aSwz[mt] = r & 7;
    }
    // B: groups -> (b0 lo-ntile)(b1 lo)(b0 hi)(b1 hi)
    const int bHalf = (lane >> 3) & 1;
    uint32_t bOff[2], bSwz[2];
#pragma unroll
    for (int ntp = 0; ntp < 2; ntp++) {
        int r = wn * 32 + ntp * 16 + (lane & 7) + ((lane >> 4) << 3);
        bOff[ntp] = r * 128;
        bSwz[ntp] = r & 7;
    }

    float acc[4][4][4];
#pragma unroll
    for (int mt = 0; mt < 4; mt++)
#pragma unroll
        for (int nt = 0; nt < 4; nt++)
#pragma unroll
            for (int j = 0; j < 4; j++) acc[mt][nt][j] = 0.0f;

#define ISSUE(kt, stg) do { \
    _Pragma("unroll") \
    for (int _i = 0; _i < 4; _i++) { \
        int _s = tid + _i * 256; \
        int _row = _s >> 3, _c16 = _s & 7; \
        uint32_t _off = _row * 128 + ((_c16 ^ (_row & 7)) << 4); \
        const float* _asrc = Abase + (size_t)_row * K + (kt) * BKF + _c16 * 4; \
        const float* _bsrc = Bbase + (size_t)_row * K + (kt) * BKF + _c16 * 4; \
        cp_async16(sbase + (stg) * STAGE_BYTES + _off, _asrc); \
        cp_async16(sbase + (stg) * STAGE_BYTES + 16384 + _off, _bsrc); \
    } \
} while (0)

#define COMPUTE(stg) do { \
    uint32_t _sA = sbase + (stg) * STAGE_BYTES; \
    uint32_t _sB = _sA + 16384; \
    _Pragma("unroll") \
    for (int ks = 0; ks < 4; ks++) { \
        uint32_t aF[4][4]; \
        _Pragma("unroll") \
        for (int mt = 0; mt < 4; mt++) { \
            uint32_t _ad = _sA + aOff[mt] + (((2 * ks + aHalf) ^ aSwz[mt]) << 4); \
            asm volatile("ldmatrix.sync.aligned.m8n8.x4.shared.b16 {%0,%1,%2,%3}, [%4];" \
                : "=r"(aF[mt][0]), "=r"(aF[mt][1]), "=r"(aF[mt][2]), "=r"(aF[mt][3]) \
                : "r"(_ad)); \
        } \
        uint32_t bF[4][2]; \
        _Pragma("unroll") \
        for (int ntp = 0; ntp < 2; ntp++) { \
            uint32_t _bd = _sB + bOff[ntp] + (((2 * ks + bHalf) ^ bSwz[ntp]) << 4); \
            asm volatile("ldmatrix.sync.aligned.m8n8.x4.shared.b16 {%0,%1,%2,%3}, [%4];" \
                : "=r"(bF[2 * ntp][0]), "=r"(bF[2 * ntp][1]), \
                  "=r"(bF[2 * ntp + 1][0]), "=r"(bF[2 * ntp + 1][1]) \
                : "r"(_bd)); \
        } \
        _Pragma("unroll") \
        for (int mt = 0; mt < 4; mt++) \
            _Pragma("unroll") \
            for (int nt = 0; nt < 4; nt++) \
                asm volatile("mma.sync.aligned.m16n8k8.row.col.f32.tf32.tf32.f32 " \
                    "{%0,%1,%2,%3}, {%4,%5,%6,%7}, {%8,%9}, {%0,%1,%2,%3};" \
                    : "+f"(acc[mt][nt][0]), "+f"(acc[mt][nt][1]), \
                      "+f"(acc[mt][nt][2]), "+f"(acc[mt][nt][3]) \
                    : "r"(aF[mt][0]), "r"(aF[mt][1]), "r"(aF[mt][2]), "r"(aF[mt][3]), \
                      "r"(bF[nt][0]), "r"(bF[nt][1])); \
    } \
} while (0)

    // prologue: stage 0, 1 in flight
    ISSUE(0, 0);
    asm volatile("cp.async.commit_group;" ::: "memory");
    ISSUE(1, 1);
    asm volatile("cp.async.commit_group;" ::: "memory");

    for (int it = 0; it < T; ++it) {
        asm volatile("cp.async.wait_group 1;" ::: "memory");
        __syncthreads();
        if (it + 2 < T) ISSUE(it + 2, (it + 2) % GSTAGES);
        asm volatile("cp.async.commit_group;" ::: "memory");
        COMPUTE(it % GSTAGES);
    }

    // epilogue
    const int g = lane >> 2, tg = lane & 3;
#pragma unroll
    for (int mt = 0; mt < 4; mt++) {
        int r0 = crow + wm * 64 + mt * 16 + g;
#pragma unroll
        for (int nt = 0; nt < 4; nt++) {
            int col = ccol + wn * 32 + nt * 8 + 2 * tg;
            float2 bv = *(const float2*)(bias + col);
            float2 o0 = make_float2(acc[mt][nt][0] + bv.x, acc[mt][nt][1] + bv.y);
            float2 o1 = make_float2(acc[mt][nt][2] + bv.x, acc[mt][nt][3] + bv.y);
            *(float2*)(C + (size_t)r0 * N + col) = o0;
            *(float2*)(C + (size_t)(r0 + 8) * N + col) = o1;
        }
    }
#undef ISSUE
#undef COMPUTE
}

// ---------------------------------------------------------------------------
// Quaternion helpers (float4 = w,x,y,z)
// ---------------------------------------------------------------------------
__device__ __forceinline__ float4 qmul(float4 a, float4 b) {
    return make_float4(
        a.x * b.x - a.y * b.y - a.z * b.z - a.w * b.w,
        a.x * b.y + a.y * b.x + a.z * b.w - a.w * b.z,
        a.x * b.z - a.y * b.w + a.z * b.x + a.w * b.y,
        a.x * b.w + a.y * b.z - a.z * b.y + a.w * b.x);
}
__device__ __forceinline__ float4 qnorm(float4 a) {
    float n = sqrtf(a.x * a.x + a.y * a.y + a.z * a.z + a.w * a.w);
    float s = 1.0f / (n + EPSQ);
    return make_float4(a.x * s, a.y * s, a.z * s, a.w * s);
}

// SU(2) exp map: v (M x 3H) -> q (M x H x 4)
__global__ void qmap_kernel(const float* __restrict__ v, float* __restrict__ q) {
    int idx = blockIdx.x * blockDim.x + threadIdx.x;
    if (idx >= PM * PH) return;
    int m = idx >> 10;
    int h = idx & 1023;
    const float* vp = v + (size_t)m * (3 * PH) + h * 3;
    float vx = vp[0], vy = vp[1], vz = vp[2];
    float th = sqrtf(vx * vx + vy * vy + vz * vz);
    float s, c;
    sincosf(th, &s, &c);
    float inv = s / (th + EPSQ);
    *(float4*)(q + (size_t)idx * 4) = make_float4(c, vx * inv, vy * inv, vz * inv);
}

// Parallel prefix quaternion product along S per (b,h) chain.
// States stored rna-tf32-rounded (they only feed the tf32 GEMM2);
// m_final written at full fp32.
__global__ __launch_bounds__(256)
void quat_scan_kernel(float* __restrict__ q, float* __restrict__ mfinal) {
    const int b = blockIdx.x >> 10;
    const int h = blockIdx.x & 1023;
    const int t = threadIdx.x;
    const size_t base = ((size_t)b * PS * PH + h) * 4;

    float4 loc[8];
#pragma unroll
    for (int j = 0; j < 8; j++)
        loc[j] = *(const float4*)(q + base + (size_t)(t * 8 + j) * (PH * 4));

    float4 agg = loc[0];
#pragma unroll
    for (int j = 1; j < 8; j++) agg = qmul(loc[j], agg);

    __shared__ float4 sbuf[256];
    sbuf[t] = agg;
    __syncthreads();
#pragma unroll
    for (int d = 1; d < 256; d <<= 1) {
        float4 other;
        const bool has = (t >= d);
        if (has) other = sbuf[t - d];
        __syncthreads();
        if (has) sbuf[t] = qmul(sbuf[t], other);
        __syncthreads();
    }
    float4 p = make_float4(1.0f, 0.0f, 0.0f, 0.0f);
    if (t > 0) p = sbuf[t - 1];
#pragma unroll
    for (int j = 0; j < 8; j++) {
        p = qmul(loc[j], p);
        float4 outq = qnorm(p);
        float4 outr = make_float4(tf32r(outq.x), tf32r(outq.y),
                                  tf32r(outq.z), tf32r(outq.w));
        *(float4*)(q + base + (size_t)(t * 8 + j) * (PH * 4)) = outr;
        if (t == 255 && j == 7)
            *(float4*)(mfinal + (size_t)blockIdx.x * 4) = outq;
    }
}

// ---------------------------------------------------------------------------
extern "C" void kernel_launch(void* const* d_in, const int* in_sizes, int n_in,
                              void* d_out, int out_size) {
    const float* x     = (const float*)d_in[0];   // (B,S,D)
    const float* W_in  = (const float*)d_in[1];   // (3H, D)
    const float* b_in  = (const float*)d_in[2];   // (3H)
    const float* W_out = (const float*)d_in[3];   // (D, 4H)
    const float* b_out = (const float*)d_in[4];   // (D)
    float* out = (float*)d_out;
    float* full_output = out;                      // (B,S,D)
    float* m_final     = out + (size_t)PM * PD;    // (B,H,4)

    float *v_ptr, *q_ptr, *a1, *b1;
    cudaGetSymbolAddress((void**)&v_ptr, g_v);
    cudaGetSymbolAddress((void**)&q_ptr, g_q);
    cudaGetSymbolAddress((void**)&a1, g_a1);
    cudaGetSymbolAddress((void**)&b1, g_b1);

    cudaFuncSetAttribute(gemm_tf32, cudaFuncAttributeMaxDynamicSharedMemorySize, GSMEM);

    // 3xTF32 split of x and W_in (K 1024 -> 3072)
    {
        size_t t4 = (size_t)PM * PD / 4;
        split3_kernel<<<(unsigned)((t4 + 255) / 256), 256>>>(x, a1, PD, 0, t4);
        t4 = (size_t)(3 * PH) * PD / 4;
        split3_kernel<<<(unsigned)((t4 + 255) / 256), 256>>>(W_in, b1, PD, 1, t4);
    }
    // GEMM1: v = x W_in^T + b_in  (M=8192, N=3072, K'=3072), ~eps^2 accurate
    {
        dim3 grid(3 * PH / BN, PM / BM);
        gemm_tf32<<<grid, 256, GSMEM>>>(a1, b1, b_in, v_ptr, 3 * PH, 3 * PD);
    }
    // exp map -> quaternions
    qmap_kernel<<<(PM * PH + 255) / 256, 256>>>(v_ptr, q_ptr);
    // prefix quaternion scan (+ m_final)
    quat_scan_kernel<<<PB * PH, 256>>>(q_ptr, m_final);
    // GEMM2: out = states W_out^T + b_out  (M=8192, N=1024, K=4096), single tf32
    {
        dim3 grid(PD / BN, PM / BM);
        gemm_tf32<<<grid, 256, GSMEM>>>(q_ptr, W_out, b_out, full_output, PD, 4 * PH);
    }
}